// round 17
// baseline (speedup 1.0000x reference)
#include <cuda_runtime.h>
#include <cuda_bf16.h>
#include <cuda_fp16.h>
#include <cstdint>
#include <math.h>

#define B_ 8
#define C_ 256
#define HID_ 64
#define H_ 64
#define W_ 64
#define N_ 4096
#define KTOT 2304          // 9 taps * 256 ci
#define NKCH 36            // KTOT / 64

// ---------------- device scratch ----------------
__device__ __align__(256) __half        g_q_h[(size_t)B_ * N_ * HID_];  // fp16 Q
__device__ __align__(256) __half        g_k_h[(size_t)B_ * N_ * HID_];  // fp16 K
__device__ __align__(256) __half        g_v_h[(size_t)B_ * C_ * N_];    // fp16 V
// x transposed: [b][n][ci]  (bf16 hi/lo for q/k conv, fp16 for v conv)
__device__ __align__(256) __nv_bfloat16 g_xt_hi[(size_t)B_ * N_ * C_];
__device__ __align__(256) __nv_bfloat16 g_xt_lo[(size_t)B_ * N_ * C_];
__device__ __align__(256) __half        g_xt_h[(size_t)B_ * N_ * C_];
// q/k weights bf16 hi/lo: [co 0..127][tap*256+ci]  (0-63 q, 64-127 k)
__device__ __align__(256) __nv_bfloat16 g_w_hi[128 * KTOT], g_w_lo[128 * KTOT];
// v weights fp16: [co 0..255][tap*256+ci]
__device__ __align__(256) __half        g_wv_h[256 * KTOT];

// ---------------- PTX helpers (sm_80-compatible only) ----------------
__device__ __forceinline__ uint32_t smem_u32(const void* p) {
    uint32_t a;
    asm("{ .reg .u64 t; cvta.to.shared.u64 t, %1; cvt.u32.u64 %0, t; }" : "=r"(a) : "l"(p));
    return a;
}
#define SWZ(x) ((uint32_t)(x) ^ ((((uint32_t)(x)) >> 3) & 0x70u))

__device__ __forceinline__ void cpa16(uint32_t dst, const void* src) {
    asm volatile("cp.async.cg.shared.global [%0], [%1], 16;" :: "r"(dst), "l"(src));
}
__device__ __forceinline__ void cpa16z(uint32_t dst, const void* src, uint32_t sz) {
    asm volatile("cp.async.cg.shared.global [%0], [%1], 16, %2;"
                 :: "r"(dst), "l"(src), "r"(sz));
}
#define CP_COMMIT() asm volatile("cp.async.commit_group;")
#define CP_WAIT(n)  asm volatile("cp.async.wait_group %0;" :: "n"(n))

__device__ __forceinline__ void ldm_x4(uint32_t a, uint32_t* r) {
    asm volatile("ldmatrix.sync.aligned.m8n8.x4.shared.b16 {%0,%1,%2,%3}, [%4];"
        : "=r"(r[0]), "=r"(r[1]), "=r"(r[2]), "=r"(r[3]) : "r"(a));
}
__device__ __forceinline__ void mma_bf16(float* d, const uint32_t* a, const uint32_t* b) {
    asm volatile("mma.sync.aligned.m16n8k16.row.col.f32.bf16.bf16.f32 "
        "{%0,%1,%2,%3}, {%4,%5,%6,%7}, {%8,%9}, {%0,%1,%2,%3};"
        : "+f"(d[0]), "+f"(d[1]), "+f"(d[2]), "+f"(d[3])
        : "r"(a[0]), "r"(a[1]), "r"(a[2]), "r"(a[3]), "r"(b[0]), "r"(b[1]));
}
__device__ __forceinline__ void mma_f16(float* d, const uint32_t* a, const uint32_t* b) {
    asm volatile("mma.sync.aligned.m16n8k16.row.col.f32.f16.f16.f32 "
        "{%0,%1,%2,%3}, {%4,%5,%6,%7}, {%8,%9}, {%0,%1,%2,%3};"
        : "+f"(d[0]), "+f"(d[1]), "+f"(d[2]), "+f"(d[3])
        : "r"(a[0]), "r"(a[1]), "r"(a[2]), "r"(a[3]), "r"(b[0]), "r"(b[1]));
}
__device__ __forceinline__ uint32_t pack_bf2(float a, float b) {
    __nv_bfloat162 t = __floats2bfloat162_rn(a, b);
    return *(uint32_t*)&t;
}

// ---------------------------------------------------------------------------
// Prep 1: x [b][ci][n] fp32 -> xt bf16 hi/lo + fp16 planes. grid(64,4,8), 256 thr
// ---------------------------------------------------------------------------
__global__ __launch_bounds__(256) void xsplit_kernel(const float* __restrict__ x)
{
    __shared__ float st[64][65];
    const int b = blockIdx.z, ci0 = blockIdx.y * 64, n0 = blockIdx.x * 64;
    const int tid = threadIdx.x, L = tid & 31, w = tid >> 5;
#pragma unroll
    for (int i = 0; i < 4; i++) {
        int j = i * 256 + tid;
        int ci = j >> 4, c4 = (j & 15) * 4;
        float4 v = *(const float4*)(x + ((size_t)b * C_ + ci0 + ci) * N_ + n0 + c4);
        st[ci][c4] = v.x; st[ci][c4 + 1] = v.y; st[ci][c4 + 2] = v.z; st[ci][c4 + 3] = v.w;
    }
    __syncthreads();
#pragma unroll
    for (int i = 0; i < 8; i++) {
        int n = w * 8 + i;
        float v0 = st[2 * L][n], v1 = st[2 * L + 1][n];
        __nv_bfloat16 h0 = __float2bfloat16(v0), h1 = __float2bfloat16(v1);
        float l0 = v0 - __bfloat162float(h0), l1 = v1 - __bfloat162float(h1);
        size_t gb = ((size_t)b * N_ + n0 + n) * C_ + ci0;
        __nv_bfloat162 hh; hh.x = h0; hh.y = h1;
        *(uint32_t*)((char*)g_xt_hi + gb * 2 + L * 4) = *(uint32_t*)&hh;
        *(uint32_t*)((char*)g_xt_lo + gb * 2 + L * 4) = pack_bf2(l0, l1);
        __half2 fh = __floats2half2_rn(v0, v1);
        *(uint32_t*)((char*)g_xt_h + gb * 2 + L * 4) = *(uint32_t*)&fh;
    }
}

// ---------------------------------------------------------------------------
// Prep 2: weights: q/k -> bf16 hi/lo [co<128]; v -> fp16 [co 0..255]
// ---------------------------------------------------------------------------
__global__ __launch_bounds__(256) void wsplit_kernel(
    const float* __restrict__ Wq, const float* __restrict__ Wk,
    const float* __restrict__ Wv)
{
    int t = blockIdx.x * 256 + threadIdx.x;   // 0..98303
    int co = t >> 8, ci = t & 255;
    if (co < 128) {
        const float* src = (co < 64) ? Wq : Wk;
        int lc = co & 63;
#pragma unroll
        for (int kk = 0; kk < 9; kk++) {
            float v = src[((size_t)lc * 256 + ci) * 9 + kk];
            __nv_bfloat16 h = __float2bfloat16(v);
            size_t o = (size_t)co * KTOT + kk * 256 + ci;
            g_w_hi[o] = h;
            g_w_lo[o] = __float2bfloat16(v - __bfloat162float(h));
        }
    } else {
        int lc = co - 128;
#pragma unroll
        for (int kk = 0; kk < 9; kk++) {
            float v = Wv[((size_t)lc * 256 + ci) * 9 + kk];
            g_wv_h[(size_t)lc * KTOT + kk * 256 + ci] = __float2half(v);
        }
    }
}

// ---------------------------------------------------------------------------
// QKV GEMM, implicit im2col (R15-proven, unchanged).
// ---------------------------------------------------------------------------
#define GM_B_OFF 98304
#define GM_TOT   196608

__device__ __forceinline__ void gemm_stage_qk(uint32_t sb, int b, int ntile,
                                              int kc, int buf, int tid) {
    const int tap = kc >> 2, cic = kc & 3;
    const int dy = tap / 3 - 1, dx = tap % 3 - 1;
#pragma unroll
    for (int i = 0; i < 4; i++) {
        int idx = tid + i * 512;
        int plane = idx >> 10;
        int rem = idx & 1023;
        int row = rem >> 3, c16 = rem & 7;
        const char* src = (plane ? (const char*)g_w_lo : (const char*)g_w_hi) +
                          ((size_t)row * KTOT + kc * 64 + c16 * 8) * 2;
        cpa16(sb + buf * 32768 + plane * 16384 + SWZ(row * 128 + c16 * 16), src);
    }
#pragma unroll
    for (int i = 0; i < 4; i++) {
        int idx = tid + i * 512;
        int plane = idx >> 10;
        int rem = idx & 1023;
        int row = rem >> 3, c16 = rem & 7;
        int n = ntile * 128 + row;
        int iy = (n >> 6) + dy;
        int ix = (n & 63) + dx;
        bool ok = (iy >= 0) && (iy < H_) && (ix >= 0) && (ix < W_);
        size_t so = ((size_t)b * N_ + (size_t)(ok ? (iy * 64 + ix) : 0)) * C_ +
                    cic * 64 + c16 * 8;
        const char* src = (plane ? (const char*)g_xt_lo : (const char*)g_xt_hi) + so * 2;
        cpa16z(sb + GM_B_OFF + buf * 32768 + plane * 16384 + SWZ(row * 128 + c16 * 16),
               src, ok ? 16u : 0u);
    }
}

__device__ __forceinline__ void gemm_stage_v(uint32_t sb, int co0v, int b, int ntile,
                                             int kc, int buf, int tid) {
    const int tap = kc >> 2, cic = kc & 3;
    const int dy = tap / 3 - 1, dx = tap % 3 - 1;
#pragma unroll
    for (int i = 0; i < 2; i++) {
        int idx = tid + i * 512;
        int row = idx >> 3, c16 = idx & 7;
        const char* src = (const char*)g_wv_h +
                          (((size_t)(co0v + row)) * KTOT + kc * 64 + c16 * 8) * 2;
        cpa16(sb + buf * 32768 + SWZ(row * 128 + c16 * 16), src);
    }
#pragma unroll
    for (int i = 0; i < 2; i++) {
        int idx = tid + i * 512;
        int row = idx >> 3, c16 = idx & 7;
        int n = ntile * 128 + row;
        int iy = (n >> 6) + dy;
        int ix = (n & 63) + dx;
        bool ok = (iy >= 0) && (iy < H_) && (ix >= 0) && (ix < W_);
        size_t so = ((size_t)b * N_ + (size_t)(ok ? (iy * 64 + ix) : 0)) * C_ +
                    cic * 64 + c16 * 8;
        cpa16z(sb + GM_B_OFF + buf * 32768 + SWZ(row * 128 + c16 * 16),
               (const char*)g_xt_h + so * 2, ok ? 16u : 0u);
    }
}

__global__ void __launch_bounds__(512, 1) gemm_qkv_kernel(
    const float* __restrict__ bq, const float* __restrict__ bk,
    const float* __restrict__ bv)
{
    extern __shared__ char smem[];
    uint32_t sb = smem_u32(smem);
    const int tid = threadIdx.x, L = tid & 31, w = tid >> 5;
    const int mw = w & 3, nw = w >> 2;
    const int cot = blockIdx.x, ntile = blockIdx.y, b = blockIdx.z;
    const bool isQK = (cot == 0);
    const int co0v = isQK ? 0 : (cot - 1) * 128;

    uint32_t RAm[2], sAm[2];
#pragma unroll
    for (int m = 0; m < 2; m++) {
        uint32_t row = (uint32_t)(mw * 32 + m * 16 + (L & 15));
        RAm[m] = row * 128;
        sAm[m] = (row & 7) << 4;
    }
    const uint32_t colA = (L & 16) ? 16u : 0u;
    uint32_t RB[2], sB[2];
#pragma unroll
    for (int j = 0; j < 2; j++) {
        uint32_t row = (uint32_t)((nw * 4 + j * 2 + (L >> 4)) * 8 + (L & 7));
        RB[j] = row * 128;
        sB[j] = (row & 7) << 4;
    }
    const uint32_t colB = (uint32_t)(L & 8) * 2;

    float d[8][4];
#pragma unroll
    for (int f = 0; f < 8; f++)
#pragma unroll
        for (int i = 0; i < 4; i++) d[f][i] = 0.f;

    if (isQK) {
        gemm_stage_qk(sb, b, ntile, 0, 0, tid);
        CP_COMMIT();
        gemm_stage_qk(sb, b, ntile, 1, 1, tid);
        CP_COMMIT();
    } else {
        gemm_stage_v(sb, co0v, b, ntile, 0, 0, tid);
        CP_COMMIT();
        gemm_stage_v(sb, co0v, b, ntile, 1, 1, tid);
        CP_COMMIT();
    }

#pragma unroll 1
    for (int kc = 0; kc < NKCH; kc++) {
        const int buf = kc % 3;
        if (kc == NKCH - 1) { CP_WAIT(0); } else { CP_WAIT(1); }
        __syncthreads();
        if (kc < NKCH - 2) {
            if (isQK) gemm_stage_qk(sb, b, ntile, kc + 2, (kc + 2) % 3, tid);
            else      gemm_stage_v(sb, co0v, b, ntile, kc + 2, (kc + 2) % 3, tid);
            CP_COMMIT();
        }

        const uint32_t Ab = sb + buf * 32768;
        const uint32_t Bb = sb + GM_B_OFF + buf * 32768;
        if (isQK) {
#pragma unroll
            for (int pass = 0; pass < 3; pass++) {
                const uint32_t Ap = Ab + ((pass == 2) ? 16384u : 0u);
                const uint32_t Bp = Bb + ((pass == 1) ? 16384u : 0u);
#pragma unroll
                for (int kk = 0; kk < 4; kk++) {
                    const uint32_t kca = (uint32_t)(kk * 32) + colA;
                    const uint32_t kcb = (uint32_t)(kk * 32) + colB;
                    uint32_t a0[4], a1[4];
                    ldm_x4(Ap + RAm[0] + (kca ^ sAm[0]), a0);
                    ldm_x4(Ap + RAm[1] + (kca ^ sAm[1]), a1);
#pragma unroll
                    for (int j = 0; j < 2; j++) {
                        uint32_t bb[4];
                        ldm_x4(Bp + RB[j] + (kcb ^ sB[j]), bb);
                        mma_bf16(d[2 * j],         a0, bb);
                        mma_bf16(d[2 * j + 1],     a0, bb + 2);
                        mma_bf16(d[4 + 2 * j],     a1, bb);
                        mma_bf16(d[4 + 2 * j + 1], a1, bb + 2);
                    }
                }
            }
        } else {
#pragma unroll
            for (int kk = 0; kk < 4; kk++) {
                const uint32_t kca = (uint32_t)(kk * 32) + colA;
                const uint32_t kcb = (uint32_t)(kk * 32) + colB;
                uint32_t a0[4], a1[4];
                ldm_x4(Ab + RAm[0] + (kca ^ sAm[0]), a0);
                ldm_x4(Ab + RAm[1] + (kca ^ sAm[1]), a1);
#pragma unroll
                for (int j = 0; j < 2; j++) {
                    uint32_t bb[4];
                    ldm_x4(Bb + RB[j] + (kcb ^ sB[j]), bb);
                    mma_f16(d[2 * j],         a0, bb);
                    mma_f16(d[2 * j + 1],     a0, bb + 2);
                    mma_f16(d[4 + 2 * j],     a1, bb);
                    mma_f16(d[4 + 2 * j + 1], a1, bb + 2);
                }
            }
        }
    }

    // ---- epilogue
    __syncthreads();
    float* sD = (float*)smem;
#pragma unroll
    for (int m = 0; m < 2; m++)
#pragma unroll
        for (int jn = 0; jn < 4; jn++) {
            int f = m * 4 + jn;
            int r0 = mw * 32 + m * 16 + (L >> 2);
            int n0 = nw * 32 + jn * 8 + 2 * (L & 3);
            sD[r0 * 130 + n0]           = d[f][0];
            sD[r0 * 130 + n0 + 1]       = d[f][1];
            sD[(r0 + 8) * 130 + n0]     = d[f][2];
            sD[(r0 + 8) * 130 + n0 + 1] = d[f][3];
        }
    __syncthreads();

    const size_t bn0 = (size_t)b * N_ + (size_t)ntile * 128;
    if (isQK) {
#pragma unroll 1
        for (int i = 0; i < 8; i++) {
            int idx = tid + i * 512;
            int n = idx >> 5, cp = idx & 31;
            size_t off = ((bn0 + n) * HID_ + 2 * cp) * 2;
            {
                float v0 = sD[(2 * cp) * 130 + n]     + bq[2 * cp];
                float v1 = sD[(2 * cp + 1) * 130 + n] + bq[2 * cp + 1];
                __half2 hh = __floats2half2_rn(v0, v1);
                *(uint32_t*)((char*)g_q_h + off) = *(uint32_t*)&hh;
            }
            {
                float v0 = sD[(64 + 2 * cp) * 130 + n]     + bk[2 * cp];
                float v1 = sD[(64 + 2 * cp + 1) * 130 + n] + bk[2 * cp + 1];
                __half2 hh = __floats2half2_rn(v0, v1);
                *(uint32_t*)((char*)g_k_h + off) = *(uint32_t*)&hh;
            }
        }
    } else {
        const size_t n0g = (size_t)ntile * 128;
#pragma unroll 1
        for (int i = 0; i < 16; i++) {
            int idx = tid + i * 512;
            int co = idx >> 6, np = idx & 63;
            float bb = bv[co0v + co];
            float v0 = sD[co * 130 + 2 * np]     + bb;
            float v1 = sD[co * 130 + 2 * np + 1] + bb;
            __half2 hh = __floats2half2_rn(v0, v1);
            size_t off = (((size_t)b * C_ + co0v + co) * N_ + n0g + 2 * np) * 2;
            *(uint32_t*)((char*)g_v_h + off) = *(uint32_t*)&hh;
        }
    }
}

// ---------------------------------------------------------------------------
// Flash attention: S fp16, online softmax, P+V fp16. 4x4 warp grid:
// warp (mw = w&3: 32 q-rows, vw = w>>2: 16 S-keys / 64 V-channels).
// Double-buffered K/V, R15 loop flow.
// ---------------------------------------------------------------------------
#define SM_Q    0                     // 16384
#define SM_P    16384                 // 16384
#define SM_RS   32768                 // 2048 (4 x 128 f32)
#define SM_MX   34816                 // 2048
#define SM_K    36864                 // 2 x 8192
#define SM_V    53248                 // 2 x 32768
#define SM_TOT  184320                // SM_V + 131072 (epilogue staging)

__device__ __forceinline__ void load_qtile(uint32_t sb, int b, int m0, int tid) {
    const char* qh = (const char*)g_q_h + ((size_t)b * N_ + m0) * HID_ * 2;
#pragma unroll
    for (int i = 0; i < 2; i++) {
        int idx = tid + i * 512;
        int row = idx >> 3, c = (idx & 7) * 16;
        cpa16(sb + SM_Q + SWZ(row * 128 + c), qh + row * 128 + c);
    }
}

__device__ __forceinline__ void load_kv(uint32_t sb, int b, int nt, int tid) {
    const int buf = nt & 1;
    const char* kh = (const char*)g_k_h + ((size_t)b * N_ + (size_t)nt * 64) * HID_ * 2;
    {
        int row = tid >> 3, c = (tid & 7) * 16;
        cpa16(sb + SM_K + buf * 8192 + SWZ(row * 128 + c), kh + row * 128 + c);
    }
    const char* vh = (const char*)g_v_h + ((size_t)b * C_ * N_ + (size_t)nt * 64) * 2;
#pragma unroll
    for (int i = 0; i < 4; i++) {
        int idx = tid + i * 512;
        int row = idx >> 3, c = (idx & 7) * 16;
        cpa16(sb + SM_V + buf * 32768 + SWZ(row * 128 + c),
              vh + (size_t)row * (N_ * 2) + c);
    }
}

__global__ void __launch_bounds__(512, 1) flash_mma_kernel(
    const float* __restrict__ x, float* __restrict__ out)
{
    extern __shared__ char smem[];
    uint32_t sb = smem_u32(smem);
    const int tid = threadIdx.x;
    const int L   = tid & 31;
    const int w   = tid >> 5;
    const int mw  = w & 3;     // 32-row group
    const int vw  = w >> 2;    // 16-key / 64-channel group
    const int b   = blockIdx.y;
    const int m0  = blockIdx.x * 128;

    load_qtile(sb, b, m0, tid);
    load_kv(sb, b, 0, tid);
    CP_COMMIT();
    load_kv(sb, b, 1, tid);
    CP_COMMIT();

    // lane constants
    uint32_t RAm[2], sAm[2];
#pragma unroll
    for (int m = 0; m < 2; m++) {
        uint32_t row = (uint32_t)(mw * 32 + m * 16 + (L & 15));
        RAm[m] = row * 128;
        sAm[m] = (row & 7) << 4;
    }
    const uint32_t colA = (L & 16) ? 16u : 0u;
    uint32_t RBk, sBk;
    {
        uint32_t row = (uint32_t)((vw * 2 + (L >> 4)) * 8 + (L & 7));
        RBk = row * 128;
        sBk = (row & 7) << 4;
    }
    const uint32_t colB = (uint32_t)(L & 8) * 2;
    const uint32_t colV = (uint32_t)((L & 8) * 2 + (L & 16) * 2);
    const int rq = L >> 2;                       // 0..7
    const int rowbase = mw * 32 + rq;            // + m*16 + s*8
    float* sRS = (float*)(smem + SM_RS);
    float* sMX = (float*)(smem + SM_MX);

    float O[16][4];
#pragma unroll
    for (int f = 0; f < 16; f++)
#pragma unroll
        for (int i = 0; i < 4; i++) O[f][i] = 0.f;
    float l[2][2]  = {{0.f, 0.f}, {0.f, 0.f}};
    float mr[2][2] = {{-INFINITY, -INFINITY}, {-INFINITY, -INFINITY}};

    for (int nt = 0; nt < 64; nt++) {
        const int buf = nt & 1;
        if (nt == 63) { CP_WAIT(0); } else { CP_WAIT(1); }
        __syncthreads();

        // ---- S[32 rows][16 keys] = Q K^T (fp16, fp32 accum)
        float d[2][2][4];
#pragma unroll
        for (int m = 0; m < 2; m++)
#pragma unroll
            for (int h = 0; h < 2; h++)
#pragma unroll
                for (int i = 0; i < 4; i++) d[m][h][i] = 0.f;

        const uint32_t kb0 = sb + SM_K + buf * 8192;
#pragma unroll
        for (int kk = 0; kk < 4; kk++) {
            const uint32_t kca = (uint32_t)(kk * 32) + colA;
            uint32_t a0[4], a1[4], bb[4];
            ldm_x4(sb + SM_Q + RAm[0] + (kca ^ sAm[0]), a0);
            ldm_x4(sb + SM_Q + RAm[1] + (kca ^ sAm[1]), a1);
            ldm_x4(kb0 + RBk + (((uint32_t)(kk * 32) + colB) ^ sBk), bb);
            mma_f16(d[0][0], a0, bb); mma_f16(d[0][1], a0, bb + 2);
            mma_f16(d[1][0], a1, bb); mma_f16(d[1][1], a1, bb + 2);
        }

        // ---- online row max (4 rows/lane; 4-lane shfl + 4-way smem exchange)
        float mx[2][2];
#pragma unroll
        for (int m = 0; m < 2; m++)
#pragma unroll
            for (int s = 0; s < 2; s++) {
                float v = fmaxf(fmaxf(d[m][0][2 * s], d[m][0][2 * s + 1]),
                                fmaxf(d[m][1][2 * s], d[m][1][2 * s + 1]));
                v = fmaxf(v, __shfl_xor_sync(~0u, v, 1));
                v = fmaxf(v, __shfl_xor_sync(~0u, v, 2));
                mx[m][s] = v;
            }
        if ((L & 3) == 0) {
#pragma unroll
            for (int m = 0; m < 2; m++)
#pragma unroll
                for (int s = 0; s < 2; s++)
                    sMX[vw * 128 + rowbase + m * 16 + s * 8] = mx[m][s];
        }
        __syncthreads();
        float mn[2][2], al[2][2];
#pragma unroll
        for (int m = 0; m < 2; m++)
#pragma unroll
            for (int s = 0; s < 2; s++) {
                int r = rowbase + m * 16 + s * 8;
                float f = fmaxf(fmaxf(sMX[r], sMX[128 + r]),
                                fmaxf(sMX[256 + r], sMX[384 + r]));
                float mnv = fmaxf(mr[m][s], f);
                al[m][s] = __expf(mr[m][s] - mnv);
                mn[m][s] = mnv;
                mr[m][s] = mnv;
            }

        // ---- p = exp(s - rowmax) -> fp16; l accumulates the ROUNDED p
        float ps[2][2] = {{0.f, 0.f}, {0.f, 0.f}};
#pragma unroll
        for (int m = 0; m < 2; m++)
#pragma unroll
            for (int h = 0; h < 2; h++) {
                float e00 = __expf(d[m][h][0] - mn[m][0]);
                float e01 = __expf(d[m][h][1] - mn[m][0]);
                float e10 = __expf(d[m][h][2] - mn[m][1]);
                float e11 = __expf(d[m][h][3] - mn[m][1]);
                __half2 p0 = __floats2half2_rn(e00, e01);
                __half2 p1 = __floats2half2_rn(e10, e11);
                float2 f0 = __half22float2(p0);
                float2 f1 = __half22float2(p1);
                ps[m][0] += f0.x + f0.y;
                ps[m][1] += f1.x + f1.y;
                uint32_t cbyte = (uint32_t)(vw * 32 + h * 16 + 4 * (L & 3));
                uint32_t rp = (uint32_t)(rowbase + m * 16);
                uint32_t swp = (rp & 7) << 4;
                *(uint32_t*)(smem + SM_P + rp * 128 + (cbyte ^ swp)) = *(uint32_t*)&p0;
                *(uint32_t*)(smem + SM_P + (rp + 8) * 128 + (cbyte ^ swp)) = *(uint32_t*)&p1;
            }
#pragma unroll
        for (int m = 0; m < 2; m++)
#pragma unroll
            for (int s = 0; s < 2; s++) {
                float v = ps[m][s];
                v += __shfl_xor_sync(~0u, v, 1);
                v += __shfl_xor_sync(~0u, v, 2);
                ps[m][s] = v;
            }
        if ((L & 3) == 0) {
#pragma unroll
            for (int m = 0; m < 2; m++)
#pragma unroll
                for (int s = 0; s < 2; s++)
                    sRS[vw * 128 + rowbase + m * 16 + s * 8] = ps[m][s];
        }
        __syncthreads();
#pragma unroll
        for (int m = 0; m < 2; m++)
#pragma unroll
            for (int s = 0; s < 2; s++) {
                int r = rowbase + m * 16 + s * 8;
                l[m][s] = l[m][s] * al[m][s] +
                          sRS[r] + sRS[128 + r] + sRS[256 + r] + sRS[384 + r];
            }

        // ---- rescale O
#pragma unroll
        for (int m = 0; m < 2; m++)
#pragma unroll
            for (int cc = 0; cc < 8; cc++) {
                O[m * 8 + cc][0] *= al[m][0]; O[m * 8 + cc][1] *= al[m][0];
                O[m * 8 + cc][2] *= al[m][1]; O[m * 8 + cc][3] *= al[m][1];
            }

        // ---- O[32 rows][64 ch] += P * V, two 32-key halves
        const uint32_t vb0 = sb + SM_V + buf * 32768;
#pragma unroll
        for (int kh = 0; kh < 2; kh++) {
            uint32_t pa[2][2][4];
#pragma unroll
            for (int m = 0; m < 2; m++)
#pragma unroll
                for (int j = 0; j < 2; j++)
                    ldm_x4(sb + SM_P + RAm[m] +
                           (((uint32_t)((kh * 2 + j) * 32) + colA) ^ sAm[m]), pa[m][j]);
#pragma unroll
            for (int cc = 0; cc < 8; cc++) {
                uint32_t row = (uint32_t)(vw * 64 + cc * 8 + (L & 7));
                uint32_t sBv = (row & 7) << 4;
                uint32_t bb[4];
                ldm_x4(vb0 + row * 128 + (((uint32_t)(kh * 64) + colV) ^ sBv), bb);
#pragma unroll
                for (int m = 0; m < 2; m++) {
                    mma_f16(O[m * 8 + cc], pa[m][0], bb);
                    mma_f16(O[m * 8 + cc], pa[m][1], bb + 2);
                }
            }
        }
        __syncthreads();   // all warps done with buf before refill
        if (nt < 62) { load_kv(sb, b, nt + 2, tid); CP_COMMIT(); }
    }

    // ---- epilogue: normalize, stage [c][m] fp32, coalesced NCHW writes
    float inv[2][2];
#pragma unroll
    for (int m = 0; m < 2; m++)
#pragma unroll
        for (int s = 0; s < 2; s++) inv[m][s] = 1.f / l[m][s];
    float* sO = (float*)(smem + SM_V);
#pragma unroll
    for (int m = 0; m < 2; m++)
#pragma unroll
        for (int cc = 0; cc < 8; cc++) {
            int c0 = vw * 64 + cc * 8 + 2 * (L & 3);
            int gg = rowbase + m * 16;
            sO[c0 * 128 + gg]           = O[m * 8 + cc][0] * inv[m][0];
            sO[(c0 + 1) * 128 + gg]     = O[m * 8 + cc][1] * inv[m][0];
            sO[c0 * 128 + gg + 8]       = O[m * 8 + cc][2] * inv[m][1];
            sO[(c0 + 1) * 128 + gg + 8] = O[m * 8 + cc][3] * inv[m][1];
        }
    __syncthreads();

    const float* xb = x   + (size_t)b * C_ * N_ + m0;
    float*       ob = out + (size_t)b * C_ * N_ + m0;
#pragma unroll 1
    for (int i = 0; i < 16; i++) {
        int idx = tid + i * 512;
        int c = idx >> 5, m4 = (idx & 31) * 4;
        float4 vo = *(float4*)(sO + (size_t)c * 128 + m4);
        float4 vx = *(const float4*)(xb + (size_t)c * N_ + m4);
        vo.x += vx.x; vo.y += vx.y; vo.z += vx.z; vo.w += vx.w;
        *(float4*)(ob + (size_t)c * N_ + m4) = vo;
    }
}

// ---------------------------------------------------------------------------
extern "C" void kernel_launch(void* const* d_in, const int* in_sizes, int n_in,
                              void* d_out, int out_size)
{
    const float* x  = (const float*)d_in[0];
    const float* Wq = (const float*)d_in[1];
    const float* bq = (const float*)d_in[2];
    const float* Wk = (const float*)d_in[3];
    const float* bk = (const float*)d_in[4];
    const float* Wv = (const float*)d_in[5];
    const float* bv = (const float*)d_in[6];
    float* out = (float*)d_out;

    xsplit_kernel<<<dim3(64, 4, 8), 256>>>(x);
    wsplit_kernel<<<384, 256>>>(Wq, Wk, Wv);

    cudaFuncSetAttribute(gemm_qkv_kernel,
                         cudaFuncAttributeMaxDynamicSharedMemorySize, GM_TOT);
    gemm_qkv_kernel<<<dim3(3, 32, 8), 512, GM_TOT>>>(bq, bk, bv);

    cudaFuncSetAttribute(flash_mma_kernel,
                         cudaFuncAttributeMaxDynamicSharedMemorySize, SM_TOT);
    flash_mma_kernel<<<dim3(32, 8), 512, SM_TOT>>>(x, out);
}